// round 13
// baseline (speedup 1.0000x reference)
#include <cuda_runtime.h>
#include <cuda_fp16.h>

#define DIMD 33
#define H_ORG 2160
#define W_ORG 3840
#define HW (H_ORG * W_ORG)          // 8294400
#define LUTN (DIMD * DIMD * DIMD)   // 35937
#define NPIX 65536                  // 256*256 small image
#define NFEAT 10
#define NBLK_FEAT 512               // 256 msb-blocks + 256 lsb-blocks
#define NPVAL (3 * 5 * 1089)        // 16335

// ---- device scratch (no allocations allowed) ----
__device__ float g_partials[NBLK_FEAT * NFEAT];

// ============================================================
// Kernel A: gather features, block-reduce partial sums.
// Blocks [0,256): msb table; blocks [256,512): lsb table.
// ============================================================
__global__ void feat_kernel(const int* __restrict__ msb, const int* __restrict__ lsb,
                            const float* __restrict__ fm, const float* __restrict__ fl) {
    bool is_lsb = blockIdx.x >= 256;
    const int*   ip  = is_lsb ? lsb : msb;
    const float* tbl = is_lsb ? fl : fm;
    int pid = (blockIdx.x & 255) * 256 + threadIdx.x;

    int ir = ip[pid], ig = ip[pid + NPIX], ib = ip[pid + 2 * NPIX];
    long ix = (long)(ir * 4096 + ig * 256 + ib * 16) * NFEAT;

    const float4* t4 = (const float4*)(tbl + ix);
    float4 a0 = __ldg(&t4[0]), a1 = __ldg(&t4[1]);
    float2 a2 = __ldg((const float2*)(tbl + ix + 8));

    float acc[NFEAT] = {a0.x, a0.y, a0.z, a0.w, a1.x, a1.y, a1.z, a1.w, a2.x, a2.y};

#pragma unroll
    for (int f = 0; f < NFEAT; f++) {
#pragma unroll
        for (int o = 16; o > 0; o >>= 1)
            acc[f] += __shfl_down_sync(0xffffffffu, acc[f], o);
    }

    __shared__ float sw[8][NFEAT];
    int warp = threadIdx.x >> 5, lane = threadIdx.x & 31;
    if (lane == 0) {
#pragma unroll
        for (int f = 0; f < NFEAT; f++) sw[warp][f] = acc[f];
    }
    __syncthreads();
    if (threadIdx.x == 0) {
#pragma unroll
        for (int f = 0; f < NFEAT; f++) {
            float s = 0.f;
#pragma unroll
            for (int w = 0; w < 8; w++) s += sw[w][f];
            g_partials[blockIdx.x * NFEAT + f] = s;
        }
    }
}

// ============================================================
// Kernel C: fused LUT-build + persistent trilinear apply.
// Every block (one wave of 148) redundantly, deterministically and
// identically computes: pooled -> mid -> weights -> Q -> P(smem)
// -> fp32 LUT -> per-cell int8/pow2 quantized s_lut (smem).
// Block b also writes d3lut cells [b*243, b*243+243) to out_lut.
// Then the streaming trilinear loop (proven R7 decode).
// ============================================================
#define APPLY_BLOCKS 148
#define APPLY_THREADS 1024
#define NG (HW / 4)     // 2073600 float4 pixel-groups
#define SLICE 243       // 148*243 = 35964 >= LUTN

__device__ __forceinline__ void corner_acc(unsigned u, float w,
                                           float& S1r, float& S1g, float& S1b, float& S2) {
    unsigned h01 = __byte_perm(u, 0x64646464u, 0x4140);  // halves: 1024+m0, 1024+m1
    unsigned h2  = __byte_perm(u, 0x64646464u, 0x4442);  // low half: 1024+m2
    float s  = __uint_as_float((u & 0xFF000000u) >> 1);  // 2^(E-127)
    float ws = w * s;
    float2 f01 = __half22float2(*(__half2*)&h01);
    float  f2  = __half2float(*(__half*)&h2);
    S1r = fmaf(ws, f01.x, S1r);
    S1g = fmaf(ws, f01.y, S1g);
    S1b = fmaf(ws, f2,   S1b);
    S2 += ws;
}

__global__ void __launch_bounds__(APPLY_THREADS, 1)
apply_kernel(const float* __restrict__ img,
             const float* __restrict__ lut_cat,
             const float* __restrict__ s_layers,
             const float* __restrict__ w_layers,
             const float* __restrict__ luts,
             float* __restrict__ out) {
    extern __shared__ float smem_dyn[];
    float*    s_P   = smem_dyn;                       // NPVAL floats
    unsigned* s_lut = (unsigned*)(smem_dyn + NPVAL);  // LUTN words

    __shared__ float s_pooled[NFEAT];
    __shared__ int   smid[NFEAT];
    __shared__ float swt[NFEAT];
    __shared__ float sQ[150];
    __shared__ float s_sl[DIMD * 5];

    int t = threadIdx.x;
    int wid = t >> 5, lane = t & 31;

    // ---- pooled: 10 warps, one feature each, fixed-order reduce ----
    if (wid < NFEAT) {
        float s = 0.f;
#pragma unroll
        for (int k = 0; k < NBLK_FEAT / 32; k++)      // 16 strided partials per lane
            s += g_partials[(lane + k * 32) * NFEAT + wid];
#pragma unroll
        for (int o = 16; o > 0; o >>= 1)
            s += __shfl_down_sync(0xffffffffu, s, o);
        if (lane == 0) s_pooled[wid] = s * (1.0f / (float)NPIX);
    }
    if (t < DIMD * 5) s_sl[t] = s_layers[t];
    __syncthreads();

    if (t < NFEAT) {
        float p = rintf(s_pooled[t] * 2.0f) * 0.5f;   // round half-even like jnp.round
        p = fminf(fmaxf(p, -16.0f), 15.5f);
        smid[t] = (int)(p * 2.0f) + 32;
    }
    __syncthreads();
    if (t < NFEAT) {
        float w = 0.f;
#pragma unroll
        for (int i = 0; i < 5; i++) {
            int index = smid[2 * i] * 64 + smid[2 * i + 1];
            w += (lut_cat[(i * 4096 + index) * NFEAT + t] - 32.0f) * 0.25f;
        }
        swt[t] = w;
    }
    __syncthreads();
    if (t < 150) {
        int ch = t / 50, s = (t / 10) % 5, w = t % 10;
        float q = 0.f;
#pragma unroll
        for (int n = 0; n < NFEAT; n++)
            q += swt[n] * luts[(s * 30 + 3 * n + ch) * NFEAT + w];
        sQ[t] = q;
    }
    __syncthreads();

    // ---- P into smem ----
    for (int i = t; i < NPVAL; i += APPLY_THREADS) {
        int chs = i / 1089;
        int q   = i % 1089;
        float p = 0.f;
#pragma unroll
        for (int w = 0; w < 10; w++)
            p += sQ[chs * 10 + w] * __ldg(&w_layers[w * 1089 + q]);
        s_P[i] = p;
    }
    __syncthreads();

    // ---- LUT build + quantize (in smem); slice-write d3lut ----
    int lo = blockIdx.x * SLICE;
    int hi = lo + SLICE;
    float* out_lut = out + 3 * HW;
    for (int v = t; v < LUTN; v += APPLY_THREADS) {
        int b = v / 1089;
        int g = (v / 33) % 33;
        int r = v % 33;
        int qr = b * 33 + g, qg = b * 33 + r, qb = g * 33 + r;
        float Lr = 0.f, Lg = 0.f, Lb = 0.f;
#pragma unroll
        for (int s = 0; s < 5; s++) {
            Lr += s_sl[r * 5 + s] * s_P[(0 * 5 + s) * 1089 + qr];
            Lg += s_sl[g * 5 + s] * s_P[(1 * 5 + s) * 1089 + qg];
            Lb += s_sl[b * 5 + s] * s_P[(2 * 5 + s) * 1089 + qb];
        }
        if (v >= lo && v < hi) {
            out_lut[v]            = Lr;
            out_lut[LUTN + v]     = Lg;
            out_lut[2 * LUTN + v] = Lb;
        }
        float cellmax = fmaxf(fmaxf(fabsf(Lr), fabsf(Lg)), fmaxf(fabsf(Lb), 1e-20f));
        unsigned eu = (__float_as_uint(cellmax) >> 23) & 0xFF;  // floor exponent (biased)
        unsigned E  = eu - 6;                                   // cellmax/scale in [64,128)
        float inv   = __uint_as_float((254u - E) << 23);        // exact 1/scale (pow2)
        int m0 = min((int)rintf(Lr * inv), 127) + 128;
        int m1 = min((int)rintf(Lg * inv), 127) + 128;
        int m2 = min((int)rintf(Lb * inv), 127) + 128;
        s_lut[v] = (unsigned)m0 | ((unsigned)m1 << 8) | ((unsigned)m2 << 16) | (E << 24);
    }
    __syncthreads();

    // ---- streaming trilinear apply (unchanged from R7/R10) ----
    const float4* R = (const float4*)(img);
    const float4* G = (const float4*)(img + HW);
    const float4* B = (const float4*)(img + 2 * HW);
    float4* OR = (float4*)(out);
    float4* OG = (float4*)(out + HW);
    float4* OB = (float4*)(out + 2 * HW);

    const float inv_binsize = (float)((DIMD - 1) / 1.000001);

    for (int i = blockIdx.x * APPLY_THREADS + t; i < NG;
         i += APPLY_BLOCKS * APPLY_THREADS) {
        float4 r4 = __ldg(&R[i]), g4 = __ldg(&G[i]), b4 = __ldg(&B[i]);

        float rr[4] = {r4.x, r4.y, r4.z, r4.w};
        float gg[4] = {g4.x, g4.y, g4.z, g4.w};
        float bb[4] = {b4.x, b4.y, b4.z, b4.w};
        float ro[4], go[4], bo[4];

#pragma unroll
        for (int k = 0; k < 4; k++) {
            float rf = rr[k] * inv_binsize;
            float gf = gg[k] * inv_binsize;
            float bf = bb[k] * inv_binsize;
            int rid0 = (int)rf, gid0 = (int)gf, bid0 = (int)bf;   // floor (inputs >= 0)
            float rd = rf - (float)rid0;
            float gd = gf - (float)gid0;
            float bd = bf - (float)bid0;
            int rid = min(rid0, DIMD - 2);
            int gid = min(gid0, DIMD - 2);
            int bid = min(bid0, DIMD - 2);

            int base = (bid * 33 + gid) * 33 + rid;

            float r1g0 = rd * (1.0f - gd);
            float r0g0 = (1.0f - gd) - r1g0;   // (1-rd)(1-gd)
            float r1g1 = rd * gd;
            float r0g1 = gd - r1g1;            // (1-rd)gd

            // plane bid
            float S1r = 0.f, S1g = 0.f, S1b = 0.f, S2 = 0.f;
            corner_acc(s_lut[base],        r0g0, S1r, S1g, S1b, S2);
            corner_acc(s_lut[base + 1],    r1g0, S1r, S1g, S1b, S2);
            corner_acc(s_lut[base + 33],   r0g1, S1r, S1g, S1b, S2);
            corner_acc(s_lut[base + 34],   r1g1, S1r, S1g, S1b, S2);
            float p0r = fmaf(-1152.0f, S2, S1r);
            float p0g = fmaf(-1152.0f, S2, S1g);
            float p0b = fmaf(-1152.0f, S2, S1b);

            // plane bid+1
            float T1r = 0.f, T1g = 0.f, T1b = 0.f, T2 = 0.f;
            corner_acc(s_lut[base + 1089], r0g0, T1r, T1g, T1b, T2);
            corner_acc(s_lut[base + 1090], r1g0, T1r, T1g, T1b, T2);
            corner_acc(s_lut[base + 1122], r0g1, T1r, T1g, T1b, T2);
            corner_acc(s_lut[base + 1123], r1g1, T1r, T1g, T1b, T2);
            float p1r = fmaf(-1152.0f, T2, T1r);
            float p1g = fmaf(-1152.0f, T2, T1g);
            float p1b = fmaf(-1152.0f, T2, T1b);

            ro[k] = fmaf(bd, p1r - p0r, p0r) + rr[k];
            go[k] = fmaf(bd, p1g - p0g, p0g) + gg[k];
            bo[k] = fmaf(bd, p1b - p0b, p0b) + bb[k];
        }

        OR[i] = make_float4(ro[0], ro[1], ro[2], ro[3]);
        OG[i] = make_float4(go[0], go[1], go[2], go[3]);
        OB[i] = make_float4(bo[0], bo[1], bo[2], bo[3]);
    }
}

// ============================================================
extern "C" void kernel_launch(void* const* d_in, const int* in_sizes, int n_in,
                              void* d_out, int out_size) {
    const int*   msb      = (const int*)d_in[0];
    const int*   lsb      = (const int*)d_in[1];
    const float* img      = (const float*)d_in[2];
    const float* fm       = (const float*)d_in[3];
    const float* fl       = (const float*)d_in[4];
    const float* lut_cat  = (const float*)d_in[5];
    const float* s_layers = (const float*)d_in[6];
    const float* w_layers = (const float*)d_in[7];
    const float* luts     = (const float*)d_in[8];
    float* out = (float*)d_out;

    const int apply_smem = NPVAL * 4 + LUTN * 4;   // 65340 + 143748 = 209088
    cudaFuncSetAttribute(apply_kernel, cudaFuncAttributeMaxDynamicSharedMemorySize,
                         apply_smem);

    feat_kernel<<<NBLK_FEAT, 256>>>(msb, lsb, fm, fl);
    apply_kernel<<<APPLY_BLOCKS, APPLY_THREADS, apply_smem>>>(
        img, lut_cat, s_layers, w_layers, luts, out);
}

// round 14
// speedup vs baseline: 1.4236x; 1.4236x over previous
#include <cuda_runtime.h>
#include <cuda_fp16.h>

#define DIMD 33
#define H_ORG 2160
#define W_ORG 3840
#define HW (H_ORG * W_ORG)          // 8294400
#define LUTN (DIMD * DIMD * DIMD)   // 35937
#define NPIX 65536                  // 256*256 small image
#define NFEAT 10
#define NBLK_FEAT 512               // 256 msb-blocks + 256 lsb-blocks

// ---- device scratch (no allocations allowed) ----
__device__ float    g_partials[NBLK_FEAT * NFEAT];
__device__ unsigned g_lutS32[LUTN];  // per-cell {m0,m1,m2, E}: int8 bias-128 + pow2 exp

// ============================================================
// Kernel A: gather features, block-reduce partial sums.
// Blocks [0,256): msb table; blocks [256,512): lsb table.
// ============================================================
__global__ void feat_kernel(const int* __restrict__ msb, const int* __restrict__ lsb,
                            const float* __restrict__ fm, const float* __restrict__ fl) {
    bool is_lsb = blockIdx.x >= 256;
    const int*   ip  = is_lsb ? lsb : msb;
    const float* tbl = is_lsb ? fl : fm;
    int pid = (blockIdx.x & 255) * 256 + threadIdx.x;

    int ir = ip[pid], ig = ip[pid + NPIX], ib = ip[pid + 2 * NPIX];
    long ix = (long)(ir * 4096 + ig * 256 + ib * 16) * NFEAT;

    const float4* t4 = (const float4*)(tbl + ix);
    float4 a0 = __ldg(&t4[0]), a1 = __ldg(&t4[1]);
    float2 a2 = __ldg((const float2*)(tbl + ix + 8));

    float acc[NFEAT] = {a0.x, a0.y, a0.z, a0.w, a1.x, a1.y, a1.z, a1.w, a2.x, a2.y};

#pragma unroll
    for (int f = 0; f < NFEAT; f++) {
#pragma unroll
        for (int o = 16; o > 0; o >>= 1)
            acc[f] += __shfl_down_sync(0xffffffffu, acc[f], o);
    }

    __shared__ float sw[8][NFEAT];
    int warp = threadIdx.x >> 5, lane = threadIdx.x & 31;
    if (lane == 0) {
#pragma unroll
        for (int f = 0; f < NFEAT; f++) sw[warp][f] = acc[f];
    }
    __syncthreads();
    if (threadIdx.x == 0) {
#pragma unroll
        for (int f = 0; f < NFEAT; f++) {
            float s = 0.f;
#pragma unroll
            for (int w = 0; w < 8; w++) s += sw[w][f];
            g_partials[blockIdx.x * NFEAT + f] = s;
        }
    }
}

// ============================================================
// Kernel B: fused pooled -> weights -> Q -> LUT -> quantize.
// One thread per LUT cell; Q (150 vals) recomputed per block (cheap).
// Per cell only 3 distinct q-columns are needed (s does not affect q),
// so P is computed on the fly from 30 COALESCED w_layers loads.
// ============================================================
#define LB_THREADS 512
#define LB_BLOCKS 71    // 71*512 = 36352 >= LUTN

__global__ void __launch_bounds__(LB_THREADS)
lutbuild_kernel(const float* __restrict__ lut_cat,
                const float* __restrict__ s_layers,
                const float* __restrict__ w_layers,
                const float* __restrict__ luts,
                float* __restrict__ out_lut) {
    __shared__ float s_pooled[NFEAT];
    __shared__ int   smid[NFEAT];
    __shared__ float swt[NFEAT];
    __shared__ float sQ[150];
    __shared__ float s_sl[DIMD * 5];

    int t = threadIdx.x;
    int wid = t >> 5, lane = t & 31;

    // pooled: 10 warps, one feature each, fixed-order reduce
    if (wid < NFEAT) {
        float s = 0.f;
#pragma unroll
        for (int k = 0; k < NBLK_FEAT / 32; k++)   // 16 strided partials per lane
            s += g_partials[(lane + k * 32) * NFEAT + wid];
#pragma unroll
        for (int o = 16; o > 0; o >>= 1)
            s += __shfl_down_sync(0xffffffffu, s, o);
        if (lane == 0) s_pooled[wid] = s * (1.0f / (float)NPIX);
    }
    if (t < DIMD * 5) s_sl[t] = s_layers[t];
    __syncthreads();

    if (t < NFEAT) {
        float p = rintf(s_pooled[t] * 2.0f) * 0.5f;   // round half-even like jnp.round
        p = fminf(fmaxf(p, -16.0f), 15.5f);
        smid[t] = (int)(p * 2.0f) + 32;
    }
    __syncthreads();
    if (t < NFEAT) {
        float w = 0.f;
#pragma unroll
        for (int i = 0; i < 5; i++) {
            int index = smid[2 * i] * 64 + smid[2 * i + 1];
            w += (lut_cat[(i * 4096 + index) * NFEAT + t] - 32.0f) * 0.25f;
        }
        swt[t] = w;
    }
    __syncthreads();
    if (t < 150) {
        int ch = t / 50, s = (t / 10) % 5, w = t % 10;
        float q = 0.f;
#pragma unroll
        for (int n = 0; n < NFEAT; n++)
            q += swt[n] * luts[(s * 30 + 3 * n + ch) * NFEAT + w];
        sQ[t] = q;
    }
    __syncthreads();

    int v = blockIdx.x * LB_THREADS + t;
    if (v >= LUTN) return;
    int b = v / 1089;
    int g = (v / 33) % 33;
    int r = v % 33;
    int qr = b * 33 + g, qg = b * 33 + r, qb = g * 33 + r;

    float Wr[10], Wg[10], Wb[10];
#pragma unroll
    for (int w = 0; w < 10; w++) {
        Wr[w] = __ldg(&w_layers[w * 1089 + qr]);
        Wg[w] = __ldg(&w_layers[w * 1089 + qg]);
        Wb[w] = __ldg(&w_layers[w * 1089 + qb]);
    }

    float Lr = 0.f, Lg = 0.f, Lb = 0.f;
#pragma unroll
    for (int s = 0; s < 5; s++) {
        float Pr = 0.f, Pg = 0.f, Pb = 0.f;
#pragma unroll
        for (int w = 0; w < 10; w++) {
            Pr += sQ[(0 * 5 + s) * 10 + w] * Wr[w];
            Pg += sQ[(1 * 5 + s) * 10 + w] * Wg[w];
            Pb += sQ[(2 * 5 + s) * 10 + w] * Wb[w];
        }
        Lr += s_sl[r * 5 + s] * Pr;
        Lg += s_sl[g * 5 + s] * Pg;
        Lb += s_sl[b * 5 + s] * Pb;
    }

    out_lut[v]            = Lr;
    out_lut[LUTN + v]     = Lg;
    out_lut[2 * LUTN + v] = Lb;

    float cellmax = fmaxf(fmaxf(fabsf(Lr), fabsf(Lg)), fmaxf(fabsf(Lb), 1e-20f));
    unsigned eu = (__float_as_uint(cellmax) >> 23) & 0xFF;   // floor exponent (biased)
    unsigned E  = eu - 6;                                    // cellmax/scale in [64,128)
    float inv   = __uint_as_float((254u - E) << 23);         // exact 1/scale (pow2)

    int m0 = min((int)rintf(Lr * inv), 127) + 128;
    int m1 = min((int)rintf(Lg * inv), 127) + 128;
    int m2 = min((int)rintf(Lb * inv), 127) + 128;
    g_lutS32[v] = (unsigned)m0 | ((unsigned)m1 << 8) | ((unsigned)m2 << 16) | (E << 24);
}

// ============================================================
// Kernel C: persistent trilinear apply; whole LUT in shared memory
// (verbatim R10 / proven 47.26us: prmt->half, pow2 scale, -1152*S2)
// ============================================================
#define APPLY_BLOCKS 148
#define APPLY_THREADS 1024
#define NG (HW / 4)   // 2073600 float4 pixel-groups

__device__ __forceinline__ void corner_acc(unsigned u, float w,
                                           float& S1r, float& S1g, float& S1b, float& S2) {
    unsigned h01 = __byte_perm(u, 0x64646464u, 0x4140);  // halves: 1024+m0, 1024+m1
    unsigned h2  = __byte_perm(u, 0x64646464u, 0x4442);  // low half: 1024+m2
    float s  = __uint_as_float((u & 0xFF000000u) >> 1);  // 2^(E-127)
    float ws = w * s;
    float2 f01 = __half22float2(*(__half2*)&h01);
    float  f2  = __half2float(*(__half*)&h2);
    S1r = fmaf(ws, f01.x, S1r);
    S1g = fmaf(ws, f01.y, S1g);
    S1b = fmaf(ws, f2,   S1b);
    S2 += ws;
}

__global__ void __launch_bounds__(APPLY_THREADS, 1)
apply_kernel(const float* __restrict__ img, float* __restrict__ out) {
    extern __shared__ unsigned s_lut[];

    for (int i = threadIdx.x; i < LUTN; i += APPLY_THREADS)
        s_lut[i] = g_lutS32[i];
    __syncthreads();

    const float4* R = (const float4*)(img);
    const float4* G = (const float4*)(img + HW);
    const float4* B = (const float4*)(img + 2 * HW);
    float4* OR = (float4*)(out);
    float4* OG = (float4*)(out + HW);
    float4* OB = (float4*)(out + 2 * HW);

    const float inv_binsize = (float)((DIMD - 1) / 1.000001);

    for (int i = blockIdx.x * APPLY_THREADS + threadIdx.x; i < NG;
         i += APPLY_BLOCKS * APPLY_THREADS) {
        float4 r4 = __ldg(&R[i]), g4 = __ldg(&G[i]), b4 = __ldg(&B[i]);

        float rr[4] = {r4.x, r4.y, r4.z, r4.w};
        float gg[4] = {g4.x, g4.y, g4.z, g4.w};
        float bb[4] = {b4.x, b4.y, b4.z, b4.w};
        float ro[4], go[4], bo[4];

#pragma unroll
        for (int k = 0; k < 4; k++) {
            float rf = rr[k] * inv_binsize;
            float gf = gg[k] * inv_binsize;
            float bf = bb[k] * inv_binsize;
            int rid0 = (int)rf, gid0 = (int)gf, bid0 = (int)bf;   // floor (inputs >= 0)
            float rd = rf - (float)rid0;
            float gd = gf - (float)gid0;
            float bd = bf - (float)bid0;
            int rid = min(rid0, DIMD - 2);
            int gid = min(gid0, DIMD - 2);
            int bid = min(bid0, DIMD - 2);

            int base = (bid * 33 + gid) * 33 + rid;

            float r1g0 = rd * (1.0f - gd);
            float r0g0 = (1.0f - gd) - r1g0;   // (1-rd)(1-gd)
            float r1g1 = rd * gd;
            float r0g1 = gd - r1g1;            // (1-rd)gd

            // plane bid
            float S1r = 0.f, S1g = 0.f, S1b = 0.f, S2 = 0.f;
            corner_acc(s_lut[base],        r0g0, S1r, S1g, S1b, S2);
            corner_acc(s_lut[base + 1],    r1g0, S1r, S1g, S1b, S2);
            corner_acc(s_lut[base + 33],   r0g1, S1r, S1g, S1b, S2);
            corner_acc(s_lut[base + 34],   r1g1, S1r, S1g, S1b, S2);
            float p0r = fmaf(-1152.0f, S2, S1r);
            float p0g = fmaf(-1152.0f, S2, S1g);
            float p0b = fmaf(-1152.0f, S2, S1b);

            // plane bid+1
            float T1r = 0.f, T1g = 0.f, T1b = 0.f, T2 = 0.f;
            corner_acc(s_lut[base + 1089], r0g0, T1r, T1g, T1b, T2);
            corner_acc(s_lut[base + 1090], r1g0, T1r, T1g, T1b, T2);
            corner_acc(s_lut[base + 1122], r0g1, T1r, T1g, T1b, T2);
            corner_acc(s_lut[base + 1123], r1g1, T1r, T1g, T1b, T2);
            float p1r = fmaf(-1152.0f, T2, T1r);
            float p1g = fmaf(-1152.0f, T2, T1g);
            float p1b = fmaf(-1152.0f, T2, T1b);

            ro[k] = fmaf(bd, p1r - p0r, p0r) + rr[k];
            go[k] = fmaf(bd, p1g - p0g, p0g) + gg[k];
            bo[k] = fmaf(bd, p1b - p0b, p0b) + bb[k];
        }

        OR[i] = make_float4(ro[0], ro[1], ro[2], ro[3]);
        OG[i] = make_float4(go[0], go[1], go[2], go[3]);
        OB[i] = make_float4(bo[0], bo[1], bo[2], bo[3]);
    }
}

// ============================================================
extern "C" void kernel_launch(void* const* d_in, const int* in_sizes, int n_in,
                              void* d_out, int out_size) {
    const int*   msb      = (const int*)d_in[0];
    const int*   lsb      = (const int*)d_in[1];
    const float* img      = (const float*)d_in[2];
    const float* fm       = (const float*)d_in[3];
    const float* fl       = (const float*)d_in[4];
    const float* lut_cat  = (const float*)d_in[5];
    const float* s_layers = (const float*)d_in[6];
    const float* w_layers = (const float*)d_in[7];
    const float* luts     = (const float*)d_in[8];
    float* out = (float*)d_out;

    const int apply_smem = LUTN * 4;   // 143748
    cudaFuncSetAttribute(apply_kernel, cudaFuncAttributeMaxDynamicSharedMemorySize,
                         apply_smem);

    feat_kernel<<<NBLK_FEAT, 256>>>(msb, lsb, fm, fl);
    lutbuild_kernel<<<LB_BLOCKS, LB_THREADS>>>(lut_cat, s_layers, w_layers, luts,
                                               out + 3 * HW);
    apply_kernel<<<APPLY_BLOCKS, APPLY_THREADS, apply_smem>>>(img, out);
}